// round 6
// baseline (speedup 1.0000x reference)
#include <cuda_runtime.h>
#include <math.h>
#include <float.h>

// Chamfer distance, B=16, N=M=2048, D=4, fp32 — single fused kernel.
// ||x-y||^2 = cp - 2 p.q + cq (eps 1e-12 negligible at rel tol 1e-3).
// Block (b, dir, pc): 16 queries/thread as 8 fma.rn.f32x2 packs vs a 32-point
// SMEM chunk. Partial mins (cq folded) -> g_part[group][pc][row] (coalesced).
// Last block per group (atomic ticket): min over 64 chunks, sqrt, group sum.
// Globally last group: fixed-order sum of 32 group sums -> out. Deterministic
// (fixed reduction orders); counters self-reset for graph replay.

#define BATCH    16
#define NP       2048
#define THREADS  128
#define QPT      16                          // queries per thread (8 packs)
#define NPACK    (QPT / 2)                   // 8
#define PS       64                          // point chunks per group
#define PTS      (NP / PS)                   // 32 points per chunk
#define NGRP     (BATCH * 2)                 // 32 groups
#define NBLK     (NGRP * PS)                 // 2048 blocks
#define RPT      (NP / THREADS)              // 16 rows per finisher thread

__device__ float g_part[(size_t)NGRP * PS * NP];  // 16 MB, L2-resident
__device__ float g_gsum[NGRP];
__device__ unsigned int g_cnt[NGRP];              // zero-init; self-resetting
__device__ unsigned int g_fc;                     // zero-init; self-resetting

// ---- packed f32x2 helpers -------------------------------------------------
__device__ __forceinline__ unsigned long long pk2(float lo, float hi) {
    unsigned long long r;
    asm("mov.b64 %0, {%1, %2};" : "=l"(r) : "f"(lo), "f"(hi));
    return r;
}
__device__ __forceinline__ void upk2(unsigned long long v, float& lo, float& hi) {
    asm("mov.b64 {%0, %1}, %2;" : "=f"(lo), "=f"(hi) : "l"(v));
}
__device__ __forceinline__ unsigned long long fma2(unsigned long long a,
                                                   unsigned long long b,
                                                   unsigned long long c) {
    unsigned long long d;
    asm("fma.rn.f32x2 %0, %1, %2, %3;" : "=l"(d) : "l"(a), "l"(b), "l"(c));
    return d;
}

// ---- fused kernel ---------------------------------------------------------
extern "C" __global__ void __launch_bounds__(THREADS, 4)
chamfer_fused(const float* __restrict__ x, const float* __restrict__ y,
              float* __restrict__ out)
{
    const int bid = blockIdx.x;
    const int pc  = bid & (PS - 1);
    const int g   = bid >> 6;                // 0..31 = b*2 + dir
    const int dir = g & 1;
    const int b   = g >> 1;

    const float* qbase = (dir == 0 ? x : y) + (size_t)b * NP * 4;
    const float* pbase = (dir == 0 ? y : x) + (size_t)b * NP * 4;

    __shared__ float4 arrA[PTS];   // (-2p.x,-2p.x,-2p.y,-2p.y)
    __shared__ float4 arrB[PTS];   // (-2p.z,-2p.z,-2p.w,-2p.w)
    __shared__ float2 arrC[PTS];   // (cp, cp)
    __shared__ float  red[THREADS];
    __shared__ int    flag;

    const int tid = threadIdx.x;

    if (tid < PTS) {
        float4 p = ((const float4*)pbase)[pc * PTS + tid];
        float cp = p.x * p.x + p.y * p.y + p.z * p.z + p.w * p.w;
        arrA[tid] = make_float4(-2.f * p.x, -2.f * p.x, -2.f * p.y, -2.f * p.y);
        arrB[tid] = make_float4(-2.f * p.z, -2.f * p.z, -2.f * p.w, -2.f * p.w);
        arrC[tid] = make_float2(cp, cp);
    }

    // 16 queries, packed pairwise (2p, 2p+1); cq recomputed in epilogue
    unsigned long long a0[NPACK], a1[NPACK], a2[NPACK], a3[NPACK];
#pragma unroll
    for (int p = 0; p < NPACK; p++) {
        float4 u = ((const float4*)qbase)[(2 * p)     * THREADS + tid];
        float4 v = ((const float4*)qbase)[(2 * p + 1) * THREADS + tid];
        a0[p] = pk2(u.x, v.x);
        a1[p] = pk2(u.y, v.y);
        a2[p] = pk2(u.z, v.z);
        a3[p] = pk2(u.w, v.w);
    }

    float m[QPT];
#pragma unroll
    for (int i = 0; i < QPT; i++) m[i] = FLT_MAX;

    __syncthreads();

    const ulonglong2* A = (const ulonglong2*)arrA;
    const ulonglong2* B = (const ulonglong2*)arrB;
    const unsigned long long* C = (const unsigned long long*)arrC;

#pragma unroll 4
    for (int j = 0; j < PTS; j++) {
        ulonglong2 va = A[j];            // broadcast LDS.128
        ulonglong2 vb = B[j];            // broadcast LDS.128
        unsigned long long vc = C[j];    // broadcast LDS.64
#pragma unroll
        for (int p = 0; p < NPACK; p++) {
            unsigned long long s = fma2(va.x, a0[p], vc);
            s = fma2(va.y, a1[p], s);
            s = fma2(vb.x, a2[p], s);
            s = fma2(vb.y, a3[p], s);
            float s0, s1;
            upk2(s, s0, s1);
            m[2*p]   = fminf(m[2*p],   s0);   // FMNMX -> alu pipe
            m[2*p+1] = fminf(m[2*p+1], s1);
        }
    }

    // epilogue: fold cq back in, coalesced store to [g][pc][row]
    float* part = &g_part[((size_t)g * PS + pc) * NP];
#pragma unroll
    for (int p = 0; p < NPACK; p++) {
        float x0, x1, y0, y1, z0, z1, w0, w1;
        upk2(a0[p], x0, x1);
        upk2(a1[p], y0, y1);
        upk2(a2[p], z0, z1);
        upk2(a3[p], w0, w1);
        part[(2 * p)     * THREADS + tid] = m[2*p]   + (x0*x0 + y0*y0 + z0*z0 + w0*w0);
        part[(2 * p + 1) * THREADS + tid] = m[2*p+1] + (x1*x1 + y1*y1 + z1*z1 + w1*w1);
    }

    __threadfence();
    if (tid == 0) {
        unsigned int v = atomicAdd(&g_cnt[g], 1u);
        flag = (v == PS - 1);
    }
    __syncthreads();
    if (!flag) return;

    // ---- group finisher: min over PS chunks, sqrt, sum over 2048 rows ----
    __threadfence();   // acquire all partials of this group
    const float* gp = &g_part[(size_t)g * PS * NP];
    float acc = 0.f;
#pragma unroll
    for (int rr = 0; rr < RPT; rr++) {
        int r = rr * THREADS + tid;
        float mn0 = FLT_MAX, mn1 = FLT_MAX, mn2 = FLT_MAX, mn3 = FLT_MAX;
#pragma unroll
        for (int pcc = 0; pcc < PS; pcc += 4) {     // coalesced per-warp LDG
            mn0 = fminf(mn0, gp[(size_t)(pcc + 0) * NP + r]);
            mn1 = fminf(mn1, gp[(size_t)(pcc + 1) * NP + r]);
            mn2 = fminf(mn2, gp[(size_t)(pcc + 2) * NP + r]);
            mn3 = fminf(mn3, gp[(size_t)(pcc + 3) * NP + r]);
        }
        float mn = fminf(fminf(mn0, mn1), fminf(mn2, mn3));
        acc += sqrtf(fmaxf(mn, 0.f));
    }

    red[tid] = acc;
    __syncthreads();
#pragma unroll
    for (int s = THREADS / 2; s > 0; s >>= 1) {
        if (tid < s) red[tid] += red[tid + s];
        __syncthreads();
    }

    if (tid == 0) {
        g_gsum[g] = red[0];
        g_cnt[g] = 0;                     // reset for graph replay
        __threadfence();
        unsigned int v = atomicAdd(&g_fc, 1u);
        flag = (v == NGRP - 1);
    }
    __syncthreads();
    if (!flag) return;

    // ---- global finisher: fixed-order sum of 32 group sums ----
    if (tid == 0) {
        __threadfence();
        float t = 0.f;
#pragma unroll
        for (int i = 0; i < NGRP; i++) t += g_gsum[i];   // fixed order
        out[0] = t;
        __threadfence();
        g_fc = 0;                         // reset for graph replay
    }
}

// ---- launch ---------------------------------------------------------------
extern "C" void kernel_launch(void* const* d_in, const int* in_sizes, int n_in,
                              void* d_out, int out_size)
{
    const float* x = (const float*)d_in[0];
    const float* y = (const float*)d_in[1];
    float* out = (float*)d_out;

    chamfer_fused<<<NBLK, THREADS>>>(x, y, out);
}

// round 7
// speedup vs baseline: 1.3115x; 1.3115x over previous
#include <cuda_runtime.h>
#include <math.h>
#include <float.h>

// Chamfer distance, B=16, N=M=2048, D=4, fp32.
// ||x-y||^2 = cp - 2 p.q + cq (eps 1e-12 negligible at rel tol 1e-3).
// Main: block = (batch, dir, point-chunk); 256 threads x 8 queries/thread
// (4 fma.rn.f32x2 packs) vs 32-point SMEM chunk (duplicated-packed).
// Cross-chunk min: atomicMax on COMPLEMENTED float bits of clamped dist^2
// (non-negative floats are bit-monotone; ~bits reverses order, so max-key =
// min-dist and the zero-initialized key acts as +inf -> no init kernel).
// Combine: 256 KB key read, sqrt, fixed-order sums, resets keys for replay.

#define BATCH    16
#define NP       2048
#define THREADS  256
#define QPT      8                           // queries per thread (4 packs)
#define NPACK    (QPT / 2)                   // 4
#define PS       64                          // point chunks
#define PTS      (NP / PS)                   // 32 points per chunk
#define NBLK     (BATCH * 2 * PS)            // 2048 blocks
#define NQTOT    (BATCH * 2 * NP)            // 65536 rows
#define CBLK     256
#define CTHR     256

__device__ unsigned int g_key[NQTOT];        // ~bits(dist^2); 0 == +inf. 256 KB
__device__ float g_psum[CBLK];
__device__ unsigned int g_count;             // zero-init; self-resetting

// ---- packed f32x2 helpers -------------------------------------------------
__device__ __forceinline__ unsigned long long pk2(float lo, float hi) {
    unsigned long long r;
    asm("mov.b64 %0, {%1, %2};" : "=l"(r) : "f"(lo), "f"(hi));
    return r;
}
__device__ __forceinline__ void upk2(unsigned long long v, float& lo, float& hi) {
    asm("mov.b64 {%0, %1}, %2;" : "=f"(lo), "=f"(hi) : "l"(v));
}
__device__ __forceinline__ unsigned long long fma2(unsigned long long a,
                                                   unsigned long long b,
                                                   unsigned long long c) {
    unsigned long long d;
    asm("fma.rn.f32x2 %0, %1, %2, %3;" : "=l"(d) : "l"(a), "l"(b), "l"(c));
    return d;
}

// ---- main kernel ----------------------------------------------------------
extern "C" __global__ void __launch_bounds__(THREADS, 4)
chamfer_main(const float* __restrict__ x, const float* __restrict__ y)
{
    const int bid = blockIdx.x;
    const int pc  = bid & (PS - 1);
    const int g   = bid >> 6;                // b*2 + dir; consecutive bids share
    const int dir = g & 1;                   // a group -> query L2 reuse
    const int b   = g >> 1;

    const float* qbase = (dir == 0 ? x : y) + (size_t)b * NP * 4;
    const float* pbase = (dir == 0 ? y : x) + (size_t)b * NP * 4;

    __shared__ float4 arrA[PTS];   // (-2p.x,-2p.x,-2p.y,-2p.y)
    __shared__ float4 arrB[PTS];   // (-2p.z,-2p.z,-2p.w,-2p.w)
    __shared__ float2 arrC[PTS];   // (cp, cp)

    const int tid = threadIdx.x;

    if (tid < PTS) {
        float4 p = ((const float4*)pbase)[pc * PTS + tid];
        float cp = p.x * p.x + p.y * p.y + p.z * p.z + p.w * p.w;
        arrA[tid] = make_float4(-2.f * p.x, -2.f * p.x, -2.f * p.y, -2.f * p.y);
        arrB[tid] = make_float4(-2.f * p.z, -2.f * p.z, -2.f * p.w, -2.f * p.w);
        arrC[tid] = make_float2(cp, cp);
    }

    // 8 queries, packed pairwise (2p, 2p+1); cq recomputed in epilogue
    unsigned long long a0[NPACK], a1[NPACK], a2[NPACK], a3[NPACK];
#pragma unroll
    for (int p = 0; p < NPACK; p++) {
        float4 u = ((const float4*)qbase)[(2 * p)     * THREADS + tid];
        float4 v = ((const float4*)qbase)[(2 * p + 1) * THREADS + tid];
        a0[p] = pk2(u.x, v.x);
        a1[p] = pk2(u.y, v.y);
        a2[p] = pk2(u.z, v.z);
        a3[p] = pk2(u.w, v.w);
    }

    float m[QPT];
#pragma unroll
    for (int i = 0; i < QPT; i++) m[i] = FLT_MAX;

    __syncthreads();

    const ulonglong2* A = (const ulonglong2*)arrA;
    const ulonglong2* B = (const ulonglong2*)arrB;
    const unsigned long long* C = (const unsigned long long*)arrC;

#pragma unroll 4
    for (int j = 0; j < PTS; j++) {
        ulonglong2 va = A[j];            // broadcast LDS.128
        ulonglong2 vb = B[j];            // broadcast LDS.128
        unsigned long long vc = C[j];    // broadcast LDS.64
#pragma unroll
        for (int p = 0; p < NPACK; p++) {
            unsigned long long s = fma2(va.x, a0[p], vc);
            s = fma2(va.y, a1[p], s);
            s = fma2(vb.x, a2[p], s);
            s = fma2(vb.y, a3[p], s);
            float s0, s1;
            upk2(s, s0, s1);
            m[2*p]   = fminf(m[2*p],   s0);   // FMNMX -> alu pipe
            m[2*p+1] = fminf(m[2*p+1], s1);
        }
    }

    // epilogue: fold cq in, clamp >=0, RED.MAX on complemented bits
    const int rowbase = g * NP;
#pragma unroll
    for (int p = 0; p < NPACK; p++) {
        float x0, x1, y0, y1, z0, z1, w0, w1;
        upk2(a0[p], x0, x1);
        upk2(a1[p], y0, y1);
        upk2(a2[p], z0, z1);
        upk2(a3[p], w0, w1);
        float d0 = fmaxf(m[2*p]   + (x0*x0 + y0*y0 + z0*z0 + w0*w0), 0.f);
        float d1 = fmaxf(m[2*p+1] + (x1*x1 + y1*y1 + z1*z1 + w1*w1), 0.f);
        int q0 = (2 * p)     * THREADS + tid;
        int q1 = (2 * p + 1) * THREADS + tid;
        atomicMax(&g_key[rowbase + q0], ~__float_as_uint(d0));
        atomicMax(&g_key[rowbase + q1], ~__float_as_uint(d1));
    }
}

// ---- combine: sqrt + deterministic sum; resets keys; last block finishes --
extern "C" __global__ void __launch_bounds__(CTHR)
chamfer_combine(float* __restrict__ out)
{
    const int qg = blockIdx.x * CTHR + threadIdx.x;   // 0..65535
    unsigned int key = g_key[qg];
    g_key[qg] = 0u;                                   // reset (= +inf) for replay
    float d = sqrtf(__uint_as_float(~key));

    __shared__ float red[CTHR];
    red[threadIdx.x] = d;
    __syncthreads();
#pragma unroll
    for (int s = CTHR / 2; s > 0; s >>= 1) {
        if (threadIdx.x < s) red[threadIdx.x] += red[threadIdx.x + s];
        __syncthreads();
    }

    __shared__ int is_last;
    if (threadIdx.x == 0) {
        g_psum[blockIdx.x] = red[0];
        __threadfence();
        unsigned int c = atomicAdd(&g_count, 1u);
        is_last = (c == CBLK - 1);
    }
    __syncthreads();

    if (is_last) {
        __threadfence();
        int t = threadIdx.x;
        red[t] = g_psum[t];               // CBLK == CTHR
        __syncthreads();
#pragma unroll
        for (int s = CTHR / 2; s > 0; s >>= 1) {
            if (t < s) red[t] += red[t + s];
            __syncthreads();
        }
        if (t == 0) {
            out[0] = red[0];
            __threadfence();
            g_count = 0;                  // reset for graph replay
        }
    }
}

// ---- launch ---------------------------------------------------------------
extern "C" void kernel_launch(void* const* d_in, const int* in_sizes, int n_in,
                              void* d_out, int out_size)
{
    const float* x = (const float*)d_in[0];
    const float* y = (const float*)d_in[1];
    float* out = (float*)d_out;

    chamfer_main<<<NBLK, THREADS>>>(x, y);
    chamfer_combine<<<CBLK, CTHR>>>(out);
}

// round 9
// speedup vs baseline: 1.3781x; 1.0508x over previous
#include <cuda_runtime.h>
#include <math.h>
#include <float.h>

// Chamfer distance, B=16, N=M=2048, D=4, fp32.
// ONE pass over the distance matrix feeds BOTH directions:
//   dist2[b,i,j] = cp_j - 2 y_j . x_i + cq_i     (eps 1e-12 negligible)
// Block = (batch, 32-column tile of y); 256 threads x 8 x-queries/thread
// (4 fma.rn.f32x2 packs) cover ALL 2048 rows -> block-local col mins are
// complete. Row mins: s_row = cp - 2p.q (cq folded post-loop). Col mins:
// s_col = s_row + cq2 (packed add) -> cmin[32] regs -> inter-lane
// transpose-reduce (lane L owns col L) -> 1 REDG per lane.
// Cross-block min: atomicMax on ~bits(clamped dist2); zero key == +inf, so
// no init kernel. Combine: vectorized key read, sqrt, fixed-order sums,
// resets keys for graph replay. All reductions order-independent or
// fixed-order -> deterministic.

#define BATCH    16
#define NP       2048
#define THREADS  256
#define QPT      8                           // queries per thread (4 packs)
#define NPACK    (QPT / 2)                   // 4
#define PTS      32                          // y-columns per block
#define TJ       (NP / PTS)                  // 64 column tiles
#define NBLK     (BATCH * TJ)                // 1024 blocks
#define NQTOT    (BATCH * 2 * NP)            // 65536 keys (x side + y side)
#define CBLK     32
#define CTHR     256
#define KPT      8                           // keys per combine thread

__device__ unsigned int g_key[NQTOT];        // ~bits(dist^2); 0 == +inf
__device__ float g_psum[CBLK];
__device__ unsigned int g_count;             // zero-init; self-resetting

// ---- packed f32x2 helpers -------------------------------------------------
__device__ __forceinline__ unsigned long long pk2(float lo, float hi) {
    unsigned long long r;
    asm("mov.b64 %0, {%1, %2};" : "=l"(r) : "f"(lo), "f"(hi));
    return r;
}
__device__ __forceinline__ void upk2(unsigned long long v, float& lo, float& hi) {
    asm("mov.b64 {%0, %1}, %2;" : "=f"(lo), "=f"(hi) : "l"(v));
}
__device__ __forceinline__ unsigned long long fma2(unsigned long long a,
                                                   unsigned long long b,
                                                   unsigned long long c) {
    unsigned long long d;
    asm("fma.rn.f32x2 %0, %1, %2, %3;" : "=l"(d) : "l"(a), "l"(b), "l"(c));
    return d;
}
__device__ __forceinline__ unsigned long long add2(unsigned long long a,
                                                   unsigned long long b) {
    unsigned long long d;
    asm("add.rn.f32x2 %0, %1, %2;" : "=l"(d) : "l"(a), "l"(b));
    return d;
}

// ---- main kernel ----------------------------------------------------------
extern "C" __global__ void __launch_bounds__(THREADS, 2)
chamfer_main(const float* __restrict__ x, const float* __restrict__ y)
{
    const int bid = blockIdx.x;
    const int tj  = bid & (TJ - 1);
    const int b   = bid >> 6;

    const float4* xb = (const float4*)(x + (size_t)b * NP * 4);
    const float4* yb = (const float4*)(y + (size_t)b * NP * 4);

    __shared__ float4 arrA[PTS];   // (-2p.x,-2p.x,-2p.y,-2p.y)
    __shared__ float4 arrB[PTS];   // (-2p.z,-2p.z,-2p.w,-2p.w)
    __shared__ float2 arrC[PTS];   // (cp, cp)

    const int tid = threadIdx.x;

    if (tid < PTS) {
        float4 p = yb[tj * PTS + tid];
        float cp = p.x * p.x + p.y * p.y + p.z * p.z + p.w * p.w;
        arrA[tid] = make_float4(-2.f * p.x, -2.f * p.x, -2.f * p.y, -2.f * p.y);
        arrB[tid] = make_float4(-2.f * p.z, -2.f * p.z, -2.f * p.w, -2.f * p.w);
        arrC[tid] = make_float2(cp, cp);
    }

    // 8 queries, packed pairwise; cq packed alongside
    unsigned long long a0[NPACK], a1[NPACK], a2[NPACK], a3[NPACK], cq2[NPACK];
#pragma unroll
    for (int p = 0; p < NPACK; p++) {
        float4 u = xb[(2 * p)     * THREADS + tid];
        float4 v = xb[(2 * p + 1) * THREADS + tid];
        a0[p] = pk2(u.x, v.x);
        a1[p] = pk2(u.y, v.y);
        a2[p] = pk2(u.z, v.z);
        a3[p] = pk2(u.w, v.w);
        cq2[p] = pk2(u.x*u.x + u.y*u.y + u.z*u.z + u.w*u.w,
                     v.x*v.x + v.y*v.y + v.z*v.z + v.w*v.w);
    }

    float m[QPT];
#pragma unroll
    for (int i = 0; i < QPT; i++) m[i] = FLT_MAX;
    float cmin[PTS];
#pragma unroll
    for (int j = 0; j < PTS; j++) cmin[j] = FLT_MAX;

    __syncthreads();

    const ulonglong2* A = (const ulonglong2*)arrA;
    const ulonglong2* B = (const ulonglong2*)arrB;
    const unsigned long long* C = (const unsigned long long*)arrC;

#pragma unroll
    for (int j = 0; j < PTS; j++) {          // fully unrolled: cmin stays in regs
        ulonglong2 va = A[j];                // broadcast LDS.128
        ulonglong2 vb = B[j];                // broadcast LDS.128
        unsigned long long vc = C[j];        // broadcast LDS.64
#pragma unroll
        for (int p = 0; p < NPACK; p++) {
            unsigned long long s = fma2(va.x, a0[p], vc);
            s = fma2(va.y, a1[p], s);
            s = fma2(vb.x, a2[p], s);
            s = fma2(vb.y, a3[p], s);        // s = cp - 2 p.q
            unsigned long long sc = add2(s, cq2[p]);  // full dist^2
            float s0, s1, c0, c1;
            upk2(s, s0, s1);
            upk2(sc, c0, c1);
            m[2*p]   = fminf(m[2*p],   s0);  // row mins (alu pipe)
            m[2*p+1] = fminf(m[2*p+1], s1);
            cmin[j]  = fminf(cmin[j], fminf(c0, c1));  // col min
        }
    }

    // ---- row epilogue: fold cq, clamp, RED.MAX on complemented bits ----
#pragma unroll
    for (int p = 0; p < NPACK; p++) {
        float cq0, cq1;
        upk2(cq2[p], cq0, cq1);
        float d0 = fmaxf(m[2*p]   + cq0, 0.f);
        float d1 = fmaxf(m[2*p+1] + cq1, 0.f);
        atomicMax(&g_key[b * NP + (2 * p)     * THREADS + tid], ~__float_as_uint(d0));
        atomicMax(&g_key[b * NP + (2 * p + 1) * THREADS + tid], ~__float_as_uint(d1));
    }

    // ---- col epilogue: inter-lane transpose-reduce, lane L owns col L ----
    const int lane = tid & 31;
#pragma unroll
    for (int off = 16; off >= 1; off >>= 1) {
#pragma unroll
        for (int k = 0; k < off; k++) {
            float mine   = (lane & off) ? cmin[k + off] : cmin[k];
            float theirs = (lane & off) ? cmin[k]       : cmin[k + off];
            float got = __shfl_xor_sync(0xffffffffu, theirs, off);
            cmin[k] = fminf(mine, got);
        }
    }
    float dcol = fmaxf(cmin[0], 0.f);        // this warp's min for column `lane`
    atomicMax(&g_key[BATCH * NP + b * NP + tj * PTS + lane], ~__float_as_uint(dcol));
}

// ---- combine: sqrt + deterministic sum; resets keys; last block finishes --
extern "C" __global__ void __launch_bounds__(CTHR)
chamfer_combine(float* __restrict__ out)
{
    const int base = (blockIdx.x * CTHR + threadIdx.x) * KPT;
    uint4 k0 = *(const uint4*)&g_key[base];
    uint4 k1 = *(const uint4*)&g_key[base + 4];
    uint4 z = make_uint4(0u, 0u, 0u, 0u);
    *(uint4*)&g_key[base]     = z;           // reset (= +inf) for graph replay
    *(uint4*)&g_key[base + 4] = z;
    float d = sqrtf(__uint_as_float(~k0.x)) + sqrtf(__uint_as_float(~k0.y))
            + sqrtf(__uint_as_float(~k0.z)) + sqrtf(__uint_as_float(~k0.w))
            + sqrtf(__uint_as_float(~k1.x)) + sqrtf(__uint_as_float(~k1.y))
            + sqrtf(__uint_as_float(~k1.z)) + sqrtf(__uint_as_float(~k1.w));

    __shared__ float red[CTHR];
    red[threadIdx.x] = d;
    __syncthreads();
#pragma unroll
    for (int s = CTHR / 2; s > 0; s >>= 1) {
        if (threadIdx.x < s) red[threadIdx.x] += red[threadIdx.x + s];
        __syncthreads();
    }

    __shared__ int is_last;
    if (threadIdx.x == 0) {
        g_psum[blockIdx.x] = red[0];
        __threadfence();
        unsigned int c = atomicAdd(&g_count, 1u);
        is_last = (c == CBLK - 1);
    }
    __syncthreads();

    if (is_last && threadIdx.x == 0) {
        __threadfence();
        float t = 0.f;
#pragma unroll
        for (int i = 0; i < CBLK; i++) t += g_psum[i];   // fixed order
        out[0] = t;
        __threadfence();
        g_count = 0;                       // reset for graph replay
    }
}

// ---- launch ---------------------------------------------------------------
extern "C" void kernel_launch(void* const* d_in, const int* in_sizes, int n_in,
                              void* d_out, int out_size)
{
    const float* x = (const float*)d_in[0];
    const float* y = (const float*)d_in[1];
    float* out = (float*)d_out;

    chamfer_main<<<NBLK, THREADS>>>(x, y);
    chamfer_combine<<<CBLK, CTHR>>>(out);
}